// round 12
// baseline (speedup 1.0000x reference)
#include <cuda_runtime.h>
#include <cuda_bf16.h>
#include <cuda_fp16.h>
#include <cstdint>

#define NN 50000
#define EE 800000
#define EPSQ 1e-16f

// ---------------- scratch (static device globals; no allocation) ----------------
__device__ __half2 g_h1h [NN * 64];    // layer1 GEMM out, fp16 (256B/row)
__device__ float   g_a1s [NN * 2];
__device__ float   g_a1d [NN * 2];
__device__ float   g_hmid[NN * 128];   // layer1 final -> layer2 GEMM input (fp32)
__device__ __half2 g_h2h [NN * 32];    // layer2 GEMM out, fp16 (128B/row)
__device__ float   g_a2s [NN];
__device__ float   g_a2d [NN];
__device__ int     g_src [EE];
__device__ int     g_dst [EE];
__device__ int     g_deg [NN + 4];
__device__ int     g_ptr [NN + 8];
__device__ int     g_pos [NN + 8];
__device__ int2    g_sedge[EE];        // (src,dst) sorted by dst
__device__ float2  g_ew1 [EE];         // per-edge softmax weights, layer1 (2 heads)
__device__ float   g_ew2 [EE];         // layer2
__device__ int     g_bsum[64];
__device__ int     g_boff[64];
__device__ int     g_e64;
__device__ int     g_arr1, g_flag1, g_arr2, g_flag2;   // grid-sync state (reset each launch)

__device__ __forceinline__ float lrelu(float x) { return x > 0.f ? x : 0.2f * x; }
__device__ __forceinline__ float elu1(float x)  { return x > 0.f ? x : expm1f(x); }

// ---------------- fused: dtype detect + zero degree + reset sync flags ----------------
__global__ void detzero_kernel(const void* ei, int E, int n) {
    int i = blockIdx.x * blockDim.x + threadIdx.x;
    if (i < n + 4) g_deg[i] = 0;
    if (blockIdx.x == 0) {
        if (threadIdx.x == 0) { g_arr1 = 0; g_flag1 = 0; g_arr2 = 0; g_flag2 = 0; }
        __shared__ int ok;
        if (threadIdx.x == 0) ok = 1;
        __syncthreads();
        int stride = E > 256 ? E / 256 : 1;
        long long idx = (long long)threadIdx.x * stride;
        if (idx < E) {
            long long v = ((const long long*)ei)[idx];
            if (v < 0 || v >= n) ok = 0;
        }
        __syncthreads();
        if (threadIdx.x == 0) g_e64 = ok;
    }
}

// ---------------- convert + degree histogram ----------------
__global__ void convert_kernel(const void* ei, int E) {
    int e = blockIdx.x * blockDim.x + threadIdx.x;
    if (e >= E) return;
    int s, d;
    if (g_e64) {
        const long long* p = (const long long*)ei;
        s = (int)p[e];
        d = (int)p[E + e];
    } else {
        const int* p = (const int*)ei;
        s = p[e];
        d = p[E + e];
    }
    g_src[e] = s;
    g_dst[e] = d;
    atomicAdd(&g_deg[d], 1);
}

// ---------------- fused scan + scatter: 49 co-resident blocks, 2 soft grid-syncs ----
__global__ void scanfused_kernel(int n, int E) {
    int b = blockIdx.x, tid = threadIdx.x;
    int nblk = gridDim.x;
    int idx0 = b * 1024 + tid * 4;
    int d0 = 0, d1 = 0, d2 = 0, d3 = 0;
    if (idx0 < n) {
        int4 v = *(const int4*)&g_deg[idx0];
        d0 = v.x;
        d1 = (idx0 + 1 < n) ? v.y : 0;
        d2 = (idx0 + 2 < n) ? v.z : 0;
        d3 = (idx0 + 3 < n) ? v.w : 0;
    }
    int tsum = d0 + d1 + d2 + d3;
    int lane = tid & 31, wid = tid >> 5;
    int inc = tsum;
    #pragma unroll
    for (int off = 1; off < 32; off <<= 1) {
        int t = __shfl_up_sync(0xffffffffu, inc, off);
        if (lane >= off) inc += t;
    }
    __shared__ int ws[8], wo[8];
    if (lane == 31) ws[wid] = inc;
    __syncthreads();
    if (tid == 0) {
        int run = 0;
        #pragma unroll
        for (int i = 0; i < 8; i++) { wo[i] = run; run += ws[i]; }
        g_bsum[b] = run;                       // block total
        __threadfence();
        int old = atomicAdd(&g_arr1, 1);
        if (old == nblk - 1) {                 // last arriving block scans block sums
            int run2 = 0;
            for (int i = 0; i < nblk; i++) {
                g_boff[i] = run2;
                run2 += *(volatile int*)&g_bsum[i];
            }
            __threadfence();
            atomicExch(&g_flag1, 1);
        }
        while (atomicAdd(&g_flag1, 0) == 0) __nanosleep(64);
    }
    __syncthreads();
    // phase C: write ptr/pos
    int base = g_boff[b] + wo[wid] + (inc - tsum);
    int p0 = base, p1 = base + d0, p2 = p1 + d1, p3 = p2 + d2;
    if (idx0 < n) {
        if (idx0 + 3 < n) {
            *(int4*)&g_ptr[idx0] = make_int4(p0, p1, p2, p3);
            *(int4*)&g_pos[idx0] = make_int4(p0, p1, p2, p3);
        } else {
            int pv[4] = {p0, p1, p2, p3};
            for (int i = 0; i < 4 && idx0 + i < n; i++) {
                g_ptr[idx0 + i] = pv[i];
                g_pos[idx0 + i] = pv[i];
            }
        }
        if (idx0 <= n - 1 && n - 1 < idx0 + 4) {
            int pv[4] = {p0, p1, p2, p3};
            int dv[4] = {d0, d1, d2, d3};
            int k = (n - 1) - idx0;
            g_ptr[n] = pv[k] + dv[k];
        }
    }
    // grid sync #2: all pos writes visible before scatter
    __threadfence();
    if (tid == 0) {
        int old = atomicAdd(&g_arr2, 1);
        if (old == nblk - 1) atomicExch(&g_flag2, 1);
        while (atomicAdd(&g_flag2, 0) == 0) __nanosleep(64);
    }
    __syncthreads();
    // scatter (strided over all edges)
    int stride = nblk * blockDim.x;
    for (int e = b * blockDim.x + tid; e < E; e += stride) {
        int d = g_dst[e];
        int p = atomicAdd(&g_pos[d], 1);
        g_sedge[p] = make_int2(g_src[e], d);
    }
}

// ---------------- per-edge softmax weights (CSR order, lane per edge) ----------------
__global__ void edgew1_kernel(int E) {
    int j = blockIdx.x * blockDim.x + threadIdx.x;
    if (j >= E) return;
    int2 e = g_sedge[j];
    float2 as = *(const float2*)&g_a1s[2 * e.x];
    float2 ad = *(const float2*)&g_a1d[2 * e.y];
    g_ew1[j] = make_float2(__expf(lrelu(as.x + ad.x)), __expf(lrelu(as.y + ad.y)));
}

__global__ void edgew2_kernel(int E) {
    int j = blockIdx.x * blockDim.x + threadIdx.x;
    if (j >= E) return;
    int2 e = g_sedge[j];
    g_ew2[j] = __expf(lrelu(g_a2s[e.x] + g_a2d[e.y]));
}

// ---------------- 3xTF32 tensor-core GEMM + fused logits + fp16 output ----------------
__device__ __forceinline__ void split_tf32(float x, uint32_t& hi, uint32_t& lo) {
    uint32_t h;
    asm("cvt.rna.tf32.f32 %0, %1;" : "=r"(h) : "f"(x));
    hi = h;
    lo = __float_as_uint(x - __uint_as_float(h));
}

__device__ __forceinline__ void mma8(float* c, const uint32_t* a, const uint32_t* b) {
    asm volatile(
        "mma.sync.aligned.m16n8k8.row.col.f32.tf32.tf32.f32 "
        "{%0,%1,%2,%3}, {%4,%5,%6,%7}, {%8,%9}, {%0,%1,%2,%3};"
        : "+f"(c[0]), "+f"(c[1]), "+f"(c[2]), "+f"(c[3])
        : "r"(a[0]), "r"(a[1]), "r"(a[2]), "r"(a[3]), "r"(b[0]), "r"(b[1]));
}

__device__ __forceinline__ void tf32_gemm_body(const float* __restrict__ A,
                                               const float* __restrict__ B,
                                               __half2* __restrict__ Ch,
                                               int n, int K, int M,
                                               const float* __restrict__ att_s,
                                               const float* __restrict__ att_d,
                                               float* __restrict__ out_s,
                                               float* __restrict__ out_d,
                                               int lstride) {
    __shared__ float As[128][36];
    __shared__ float Bs[32][68];
    __shared__ float s_as[64], s_ad[64];
    int tid  = threadIdx.x;
    int warp = tid >> 5, lane = tid & 31;
    int qr = lane >> 2, qc = lane & 3;
    int warpM = (warp >> 1) * 32;
    int warpN = (warp & 1) * 32;
    int rowBase = blockIdx.y * 128;
    int colBase = blockIdx.x * 64;
    int head    = blockIdx.x;
    int Mh      = M >> 1;

    if (tid < 64) {
        s_as[tid] = att_s[head * 64 + tid];
        s_ad[tid] = att_d[head * 64 + tid];
    }

    float acc[2][4][4];
    #pragma unroll
    for (int mt = 0; mt < 2; mt++)
        #pragma unroll
        for (int nt = 0; nt < 4; nt++)
            #pragma unroll
            for (int i = 0; i < 4; i++) acc[mt][nt][i] = 0.f;

    float4 pa[4], pb[2];
    #pragma unroll
    for (int i = 0; i < 4; i++) {
        int f = tid + 256 * i;
        int r = f >> 3, c4 = (f & 7) * 4;
        pa[i] = make_float4(0.f, 0.f, 0.f, 0.f);
        if (rowBase + r < n)
            pa[i] = *(const float4*)&A[(size_t)(rowBase + r) * K + c4];
    }
    #pragma unroll
    for (int i = 0; i < 2; i++) {
        int f = tid + 256 * i;
        int r = f >> 4, c4 = (f & 15) * 4;
        pb[i] = *(const float4*)&B[(size_t)r * M + colBase + c4];
    }

    int nsteps = K >> 5;
    for (int t = 0; t < nsteps; t++) {
        #pragma unroll
        for (int i = 0; i < 4; i++) {
            int f = tid + 256 * i;
            *(float4*)&As[f >> 3][(f & 7) * 4] = pa[i];
        }
        #pragma unroll
        for (int i = 0; i < 2; i++) {
            int f = tid + 256 * i;
            *(float4*)&Bs[f >> 4][(f & 15) * 4] = pb[i];
        }
        __syncthreads();
        if (t + 1 < nsteps) {
            int k0 = (t + 1) * 32;
            #pragma unroll
            for (int i = 0; i < 4; i++) {
                int f = tid + 256 * i;
                int r = f >> 3, c4 = (f & 7) * 4;
                pa[i] = make_float4(0.f, 0.f, 0.f, 0.f);
                if (rowBase + r < n)
                    pa[i] = *(const float4*)&A[(size_t)(rowBase + r) * K + k0 + c4];
            }
            #pragma unroll
            for (int i = 0; i < 2; i++) {
                int f = tid + 256 * i;
                int r = f >> 4, c4 = (f & 15) * 4;
                pb[i] = *(const float4*)&B[(size_t)(k0 + r) * M + colBase + c4];
            }
        }
        #pragma unroll
        for (int kk = 0; kk < 4; kk++) {
            int kb = kk * 8 + qc;
            uint32_t ah[2][4], al[2][4], bh[4][2], bl[4][2];
            #pragma unroll
            for (int mt = 0; mt < 2; mt++) {
                int r0 = warpM + mt * 16 + qr;
                split_tf32(As[r0][kb],         ah[mt][0], al[mt][0]);
                split_tf32(As[r0 + 8][kb],     ah[mt][1], al[mt][1]);
                split_tf32(As[r0][kb + 4],     ah[mt][2], al[mt][2]);
                split_tf32(As[r0 + 8][kb + 4], ah[mt][3], al[mt][3]);
            }
            #pragma unroll
            for (int nt = 0; nt < 4; nt++) {
                int nn = warpN + nt * 8 + qr;
                split_tf32(Bs[kb][nn],     bh[nt][0], bl[nt][0]);
                split_tf32(Bs[kb + 4][nn], bh[nt][1], bl[nt][1]);
            }
            #pragma unroll
            for (int mt = 0; mt < 2; mt++)
                #pragma unroll
                for (int nt = 0; nt < 4; nt++) {
                    mma8(acc[mt][nt], ah[mt], bl[nt]);
                    mma8(acc[mt][nt], al[mt], bh[nt]);
                    mma8(acc[mt][nt], ah[mt], bh[nt]);
                }
        }
        __syncthreads();
    }

    // ---- epilogue 1: fp16 output ----
    #pragma unroll
    for (int mt = 0; mt < 2; mt++) {
        int r0 = rowBase + warpM + mt * 16 + qr;
        #pragma unroll
        for (int nt = 0; nt < 4; nt++) {
            int cc = colBase + warpN + nt * 8 + qc * 2;
            if (r0 < n)
                Ch[(size_t)r0 * Mh + (cc >> 1)] = __floats2half2_rn(acc[mt][nt][0], acc[mt][nt][1]);
            if (r0 + 8 < n)
                Ch[(size_t)(r0 + 8) * Mh + (cc >> 1)] = __floats2half2_rn(acc[mt][nt][2], acc[mt][nt][3]);
        }
    }

    // ---- epilogue 2: fused attention logits ----
    float psum[4] = {0.f, 0.f, 0.f, 0.f};
    float pdsum[4] = {0.f, 0.f, 0.f, 0.f};
    #pragma unroll
    for (int mt = 0; mt < 2; mt++)
        #pragma unroll
        for (int nt = 0; nt < 4; nt++) {
            int cl = warpN + nt * 8 + qc * 2;
            float as0 = s_as[cl], as1 = s_as[cl + 1];
            float ad0 = s_ad[cl], ad1 = s_ad[cl + 1];
            psum [mt * 2 + 0] += acc[mt][nt][0] * as0 + acc[mt][nt][1] * as1;
            pdsum[mt * 2 + 0] += acc[mt][nt][0] * ad0 + acc[mt][nt][1] * ad1;
            psum [mt * 2 + 1] += acc[mt][nt][2] * as0 + acc[mt][nt][3] * as1;
            pdsum[mt * 2 + 1] += acc[mt][nt][2] * ad0 + acc[mt][nt][3] * ad1;
        }
    #pragma unroll
    for (int off = 1; off <= 2; off <<= 1)
        #pragma unroll
        for (int j = 0; j < 4; j++) {
            psum[j]  += __shfl_xor_sync(0xffffffffu, psum[j],  off);
            pdsum[j] += __shfl_xor_sync(0xffffffffu, pdsum[j], off);
        }
    float* red_s = &As[0][0];
    float* red_d = &As[0][0] + 128;
    __syncthreads();
    if ((warp & 1) == 0 && qc == 0) {
        #pragma unroll
        for (int j = 0; j < 4; j++) {
            int row = warpM + (j >> 1) * 16 + (j & 1) * 8 + qr;
            red_s[row] = psum[j];
            red_d[row] = pdsum[j];
        }
    }
    __syncthreads();
    if ((warp & 1) == 1 && qc == 0) {
        #pragma unroll
        for (int j = 0; j < 4; j++) {
            int row = warpM + (j >> 1) * 16 + (j & 1) * 8 + qr;
            int grow = rowBase + row;
            if (grow < n) {
                out_s[(size_t)grow * lstride + head] = red_s[row] + psum[j];
                out_d[(size_t)grow * lstride + head] = red_d[row] + pdsum[j];
            }
        }
    }
}

__global__ void sgemm1_kernel(const float* __restrict__ A, const float* __restrict__ B,
                              const float* __restrict__ att_s, const float* __restrict__ att_d,
                              int n) {
    tf32_gemm_body(A, B, g_h1h, n, 128, 128, att_s, att_d, g_a1s, g_a1d, 2);
}
__global__ void sgemm2_kernel(const float* __restrict__ B,
                              const float* __restrict__ att_s, const float* __restrict__ att_d,
                              int n) {
    tf32_gemm_body(g_hmid, B, g_h2h, n, 128, 64, att_s, att_d, g_a2s, g_a2d, 1);
}

// ---------------- layer1 gather: streaming, no shfl ----------------
__global__ void gather1_kernel(const float* __restrict__ b1, int n) {
    int w = (blockIdx.x * blockDim.x + threadIdx.x) >> 5;
    if (w >= n) return;
    int lane = threadIdx.x & 31;
    int c0 = lane * 4;
    float ws0 = __expf(lrelu(g_a1s[2 * w]     + g_a1d[2 * w]));
    float ws1 = __expf(lrelu(g_a1s[2 * w + 1] + g_a1d[2 * w + 1]));
    uint2 us = *(const uint2*)&g_h1h[(size_t)w * 64 + lane * 2];
    float2 f0 = __half22float2(*reinterpret_cast<__half2*>(&us.x));
    float2 f1 = __half22float2(*reinterpret_cast<__half2*>(&us.y));
    float wws = (c0 < 64) ? ws0 : ws1;
    float4 acc = make_float4(f0.x * wws, f0.y * wws, f1.x * wws, f1.y * wws);
    float den0 = ws0, den1 = ws1;
    int start = g_ptr[w], end = g_ptr[w + 1];
    #pragma unroll 4
    for (int j = start; j < end; j++) {
        int s = g_sedge[j].x;
        float2 wv = g_ew1[j];
        uint2 u = *(const uint2*)&g_h1h[(size_t)s * 64 + lane * 2];
        float2 h0 = __half22float2(*reinterpret_cast<__half2*>(&u.x));
        float2 h1 = __half22float2(*reinterpret_cast<__half2*>(&u.y));
        float ww = (c0 < 64) ? wv.x : wv.y;
        acc.x += h0.x * ww; acc.y += h0.y * ww; acc.z += h1.x * ww; acc.w += h1.y * ww;
        den0 += wv.x; den1 += wv.y;
    }
    float r = 1.0f / (((c0 < 64) ? den0 : den1) + EPSQ);
    float4 o;
    o.x = elu1(acc.x * r + b1[c0]);
    o.y = elu1(acc.y * r + b1[c0 + 1]);
    o.z = elu1(acc.z * r + b1[c0 + 2]);
    o.w = elu1(acc.w * r + b1[c0 + 3]);
    *(float4*)&g_hmid[(size_t)w * 128 + c0] = o;
}

// ---------------- fused layer2 gather + final head: 16 nodes / 512-thread block --
__global__ void gather2final_kernel(const float* __restrict__ b2,
                                    const float* __restrict__ lin_w,
                                    const float* __restrict__ lin_b,
                                    float* __restrict__ out, int n) {
    __shared__ float sw[1024];
    __shared__ float st[16][66];
    int tid = threadIdx.x;
    int wid = tid >> 5, lane = tid & 31;
    int nb = blockIdx.x * 16;
    int node = nb + wid;
    sw[tid] = lin_w[tid];
    sw[tid + 512] = lin_w[tid + 512];
    int c0 = lane * 2;
    float2 o = make_float2(0.f, 0.f);
    if (node < n) {
        float ws0 = __expf(lrelu(g_a2s[node] + g_a2d[node]));
        float2 hs = __half22float2(g_h2h[(size_t)node * 32 + lane]);
        float2 acc = make_float2(hs.x * ws0, hs.y * ws0);
        float den = ws0;
        int start = g_ptr[node], end = g_ptr[node + 1];
        #pragma unroll 4
        for (int j = start; j < end; j++) {
            int s = g_sedge[j].x;
            float wv = g_ew2[j];
            float2 h = __half22float2(g_h2h[(size_t)s * 32 + lane]);
            acc.x += h.x * wv; acc.y += h.y * wv;
            den += wv;
        }
        float r = 1.0f / (den + EPSQ);
        o.x = elu1(acc.x * r + b2[c0]);
        o.y = elu1(acc.y * r + b2[c0 + 1]);
    }
    st[wid][c0] = o.x;
    st[wid][c0 + 1] = o.y;
    __syncthreads();
    if (tid < 256) {
        int g = tid >> 4, o16 = tid & 15;
        int nd = nb + g;
        if (nd < n) {
            float acc = lin_b[o16];
            #pragma unroll
            for (int c = 0; c < 64; c++)
                acc += st[g][c] * sw[c * 16 + o16];
            out[(size_t)nd * 16 + o16] = 1.0f / (1.0f + __expf(-acc));
        }
    }
}

// ---------------- launcher ----------------
extern "C" void kernel_launch(void* const* d_in, const int* in_sizes, int n_in,
                              void* d_out, int out_size) {
    const float* x        = (const float*)d_in[0];
    const void*  ei       = d_in[1];
    const float* W1       = (const float*)d_in[2];
    const float* att_src1 = (const float*)d_in[3];
    const float* att_dst1 = (const float*)d_in[4];
    const float* b1       = (const float*)d_in[5];
    const float* W2       = (const float*)d_in[6];
    const float* att_src2 = (const float*)d_in[7];
    const float* att_dst2 = (const float*)d_in[8];
    const float* b2       = (const float*)d_in[9];
    const float* lin_w    = (const float*)d_in[10];
    const float* lin_b    = (const float*)d_in[11];
    float*       out      = (float*)d_out;

    int n = in_sizes[0] / 128;        // 50000
    int E = in_sizes[1] / 2;          // 800000
    int nblk = (n + 1023) / 1024;     // 49 scan tiles (co-resident)
    int gy   = (n + 127) / 128;       // 391 gemm row tiles

    // CSR build
    detzero_kernel <<<(n + 4 + 255) / 256, 256>>>(ei, E, n);
    convert_kernel <<<(E + 255) / 256, 256>>>(ei, E);
    scanfused_kernel<<<nblk, 256>>>(n, E);

    // layer 1
    sgemm1_kernel <<<dim3(2, gy), 256>>>(x, W1, att_src1, att_dst1, n);
    edgew1_kernel <<<(E + 255) / 256, 256>>>(E);
    gather1_kernel<<<(n + 7) / 8, 256>>>(b1, n);
    // layer 2
    sgemm2_kernel <<<dim3(1, gy), 256>>>(W2, att_src2, att_dst2, n);
    edgew2_kernel <<<(E + 255) / 256, 256>>>(E);
    gather2final_kernel<<<(n + 15) / 16, 512>>>(b2, lin_w, lin_b, out, n);
}

// round 13
// speedup vs baseline: 1.2233x; 1.2233x over previous
#include <cuda_runtime.h>
#include <cuda_bf16.h>
#include <cuda_fp16.h>
#include <cstdint>

#define NN 50000
#define EE 800000
#define EPSQ 1e-16f

// ---------------- scratch (static device globals; no allocation) ----------------
__device__ __half2 g_h1h [NN * 64];    // layer1 GEMM out, fp16 (256B/row)
__device__ float   g_a1s [NN * 2];
__device__ float   g_a1d [NN * 2];
__device__ float   g_hmid[NN * 128];   // layer1 final -> layer2 GEMM input (fp32)
__device__ __half2 g_h2h [NN * 32];    // layer2 GEMM out, fp16 (128B/row)
__device__ float   g_a2s [NN];
__device__ float   g_a2d [NN];
__device__ int     g_src [EE];
__device__ int     g_dst [EE];
__device__ int     g_deg [NN + 4];
__device__ int     g_ptr [NN + 8];
__device__ int     g_pos [NN + 8];
__device__ int2    g_sedge[EE];        // (src,dst) sorted by dst
__device__ float2  g_ew1 [EE];         // per-edge softmax weights, layer1 (2 heads)
__device__ float   g_ew2 [EE];         // layer2
__device__ int     g_bsum[64];
__device__ int     g_boff[64];
__device__ int     g_e64;

__device__ __forceinline__ float lrelu(float x) { return x > 0.f ? x : 0.2f * x; }
__device__ __forceinline__ float elu1(float x)  { return x > 0.f ? x : expm1f(x); }

// ---------------- fused: edge dtype detect (block 0) + zero degree ----------------
__global__ void detzero_kernel(const void* ei, int E, int n) {
    int i = blockIdx.x * blockDim.x + threadIdx.x;
    if (i < n + 4) g_deg[i] = 0;
    if (blockIdx.x == 0) {
        __shared__ int ok;
        if (threadIdx.x == 0) ok = 1;
        __syncthreads();
        int stride = E > 256 ? E / 256 : 1;
        long long idx = (long long)threadIdx.x * stride;
        if (idx < E) {
            long long v = ((const long long*)ei)[idx];
            if (v < 0 || v >= n) ok = 0;
        }
        __syncthreads();
        if (threadIdx.x == 0) g_e64 = ok;
    }
}

// ---------------- convert + degree histogram ----------------
__global__ void convert_kernel(const void* ei, int E) {
    int e = blockIdx.x * blockDim.x + threadIdx.x;
    if (e >= E) return;
    int s, d;
    if (g_e64) {
        const long long* p = (const long long*)ei;
        s = (int)p[e];
        d = (int)p[E + e];
    } else {
        const int* p = (const int*)ei;
        s = p[e];
        d = p[E + e];
    }
    g_src[e] = s;
    g_dst[e] = d;
    atomicAdd(&g_deg[d], 1);
}

// ---------------- 3-phase parallel exclusive scan ----------------
__global__ void scanA_kernel(int n) {
    int b = blockIdx.x;
    int base = b * 1024 + threadIdx.x * 4;
    int s = 0;
    if (base < n) {
        int4 v = *(const int4*)&g_deg[base];
        s = v.x + ((base + 1 < n) ? v.y : 0) + ((base + 2 < n) ? v.z : 0) + ((base + 3 < n) ? v.w : 0);
    }
    int lane = threadIdx.x & 31, wid = threadIdx.x >> 5;
    #pragma unroll
    for (int off = 16; off >= 1; off >>= 1) s += __shfl_xor_sync(0xffffffffu, s, off);
    __shared__ int ws[8];
    if (lane == 0) ws[wid] = s;
    __syncthreads();
    if (threadIdx.x == 0) {
        int t = 0;
        #pragma unroll
        for (int i = 0; i < 8; i++) t += ws[i];
        g_bsum[b] = t;
    }
}

__global__ void scanB_kernel(int nb) {
    int tid = threadIdx.x;
    int lane = tid & 31, w = tid >> 5;
    int v = (tid < nb) ? g_bsum[tid] : 0;
    int inc = v;
    #pragma unroll
    for (int off = 1; off < 32; off <<= 1) {
        int t = __shfl_up_sync(0xffffffffu, inc, off);
        if (lane >= off) inc += t;
    }
    __shared__ int wt[2];
    if (lane == 31) wt[w] = inc;
    __syncthreads();
    if (w == 1) inc += wt[0];
    g_boff[tid] = inc - v;
}

__global__ void scanC_kernel(int n) {
    int b = blockIdx.x;
    int idx0 = b * 1024 + threadIdx.x * 4;
    int d0 = 0, d1 = 0, d2 = 0, d3 = 0;
    if (idx0 < n) {
        int4 v = *(const int4*)&g_deg[idx0];
        d0 = v.x;
        d1 = (idx0 + 1 < n) ? v.y : 0;
        d2 = (idx0 + 2 < n) ? v.z : 0;
        d3 = (idx0 + 3 < n) ? v.w : 0;
    }
    int tsum = d0 + d1 + d2 + d3;
    int lane = threadIdx.x & 31, wid = threadIdx.x >> 5;
    int inc = tsum;
    #pragma unroll
    for (int off = 1; off < 32; off <<= 1) {
        int t = __shfl_up_sync(0xffffffffu, inc, off);
        if (lane >= off) inc += t;
    }
    __shared__ int ws[8];
    if (lane == 31) ws[wid] = inc;
    __syncthreads();
    __shared__ int wo[8];
    if (threadIdx.x == 0) {
        int run = 0;
        #pragma unroll
        for (int i = 0; i < 8; i++) { wo[i] = run; run += ws[i]; }
    }
    __syncthreads();
    int base = g_boff[b] + wo[wid] + (inc - tsum);
    int p0 = base, p1 = base + d0, p2 = p1 + d1, p3 = p2 + d2;
    if (idx0 < n) {
        if (idx0 + 3 < n) {
            *(int4*)&g_ptr[idx0] = make_int4(p0, p1, p2, p3);
            *(int4*)&g_pos[idx0] = make_int4(p0, p1, p2, p3);
        } else {
            int pv[4] = {p0, p1, p2, p3};
            for (int i = 0; i < 4 && idx0 + i < n; i++) {
                g_ptr[idx0 + i] = pv[i];
                g_pos[idx0 + i] = pv[i];
            }
        }
        if (idx0 <= n - 1 && n - 1 < idx0 + 4) {
            int pv[4] = {p0, p1, p2, p3};
            int dv[4] = {d0, d1, d2, d3};
            int k = (n - 1) - idx0;
            g_ptr[n] = pv[k] + dv[k];
        }
    }
}

// ---------------- scatter (src,dst) into dst-sorted order (full grid) ----------------
__global__ void scatter_kernel(int E) {
    int e = blockIdx.x * blockDim.x + threadIdx.x;
    if (e >= E) return;
    int d = g_dst[e];
    int p = atomicAdd(&g_pos[d], 1);
    g_sedge[p] = make_int2(g_src[e], d);
}

// ---------------- per-edge softmax weights (CSR order, lane per edge) ----------------
__global__ void edgew1_kernel(int E) {
    int j = blockIdx.x * blockDim.x + threadIdx.x;
    if (j >= E) return;
    int2 e = g_sedge[j];
    float2 as = *(const float2*)&g_a1s[2 * e.x];
    float2 ad = *(const float2*)&g_a1d[2 * e.y];
    g_ew1[j] = make_float2(__expf(lrelu(as.x + ad.x)), __expf(lrelu(as.y + ad.y)));
}

__global__ void edgew2_kernel(int E) {
    int j = blockIdx.x * blockDim.x + threadIdx.x;
    if (j >= E) return;
    int2 e = g_sedge[j];
    g_ew2[j] = __expf(lrelu(g_a2s[e.x] + g_a2d[e.y]));
}

// ---------------- 3xTF32 tensor-core GEMM + fused logits + fp16 output ----------------
__device__ __forceinline__ void split_tf32(float x, uint32_t& hi, uint32_t& lo) {
    uint32_t h;
    asm("cvt.rna.tf32.f32 %0, %1;" : "=r"(h) : "f"(x));
    hi = h;
    lo = __float_as_uint(x - __uint_as_float(h));
}

__device__ __forceinline__ void mma8(float* c, const uint32_t* a, const uint32_t* b) {
    asm volatile(
        "mma.sync.aligned.m16n8k8.row.col.f32.tf32.tf32.f32 "
        "{%0,%1,%2,%3}, {%4,%5,%6,%7}, {%8,%9}, {%0,%1,%2,%3};"
        : "+f"(c[0]), "+f"(c[1]), "+f"(c[2]), "+f"(c[3])
        : "r"(a[0]), "r"(a[1]), "r"(a[2]), "r"(a[3]), "r"(b[0]), "r"(b[1]));
}

__device__ __forceinline__ void tf32_gemm_body(const float* __restrict__ A,
                                               const float* __restrict__ B,
                                               __half2* __restrict__ Ch,
                                               int n, int K, int M,
                                               const float* __restrict__ att_s,
                                               const float* __restrict__ att_d,
                                               float* __restrict__ out_s,
                                               float* __restrict__ out_d,
                                               int lstride) {
    __shared__ float As[128][36];
    __shared__ float Bs[32][68];
    __shared__ float s_as[64], s_ad[64];
    int tid  = threadIdx.x;
    int warp = tid >> 5, lane = tid & 31;
    int qr = lane >> 2, qc = lane & 3;
    int warpM = (warp >> 1) * 32;
    int warpN = (warp & 1) * 32;
    int rowBase = blockIdx.y * 128;
    int colBase = blockIdx.x * 64;
    int head    = blockIdx.x;
    int Mh      = M >> 1;

    if (tid < 64) {
        s_as[tid] = att_s[head * 64 + tid];
        s_ad[tid] = att_d[head * 64 + tid];
    }

    float acc[2][4][4];
    #pragma unroll
    for (int mt = 0; mt < 2; mt++)
        #pragma unroll
        for (int nt = 0; nt < 4; nt++)
            #pragma unroll
            for (int i = 0; i < 4; i++) acc[mt][nt][i] = 0.f;

    float4 pa[4], pb[2];
    #pragma unroll
    for (int i = 0; i < 4; i++) {
        int f = tid + 256 * i;
        int r = f >> 3, c4 = (f & 7) * 4;
        pa[i] = make_float4(0.f, 0.f, 0.f, 0.f);
        if (rowBase + r < n)
            pa[i] = *(const float4*)&A[(size_t)(rowBase + r) * K + c4];
    }
    #pragma unroll
    for (int i = 0; i < 2; i++) {
        int f = tid + 256 * i;
        int r = f >> 4, c4 = (f & 15) * 4;
        pb[i] = *(const float4*)&B[(size_t)r * M + colBase + c4];
    }

    int nsteps = K >> 5;
    for (int t = 0; t < nsteps; t++) {
        #pragma unroll
        for (int i = 0; i < 4; i++) {
            int f = tid + 256 * i;
            *(float4*)&As[f >> 3][(f & 7) * 4] = pa[i];
        }
        #pragma unroll
        for (int i = 0; i < 2; i++) {
            int f = tid + 256 * i;
            *(float4*)&Bs[f >> 4][(f & 15) * 4] = pb[i];
        }
        __syncthreads();
        if (t + 1 < nsteps) {
            int k0 = (t + 1) * 32;
            #pragma unroll
            for (int i = 0; i < 4; i++) {
                int f = tid + 256 * i;
                int r = f >> 3, c4 = (f & 7) * 4;
                pa[i] = make_float4(0.f, 0.f, 0.f, 0.f);
                if (rowBase + r < n)
                    pa[i] = *(const float4*)&A[(size_t)(rowBase + r) * K + k0 + c4];
            }
            #pragma unroll
            for (int i = 0; i < 2; i++) {
                int f = tid + 256 * i;
                int r = f >> 4, c4 = (f & 15) * 4;
                pb[i] = *(const float4*)&B[(size_t)(k0 + r) * M + colBase + c4];
            }
        }
        #pragma unroll
        for (int kk = 0; kk < 4; kk++) {
            int kb = kk * 8 + qc;
            uint32_t ah[2][4], al[2][4], bh[4][2], bl[4][2];
            #pragma unroll
            for (int mt = 0; mt < 2; mt++) {
                int r0 = warpM + mt * 16 + qr;
                split_tf32(As[r0][kb],         ah[mt][0], al[mt][0]);
                split_tf32(As[r0 + 8][kb],     ah[mt][1], al[mt][1]);
                split_tf32(As[r0][kb + 4],     ah[mt][2], al[mt][2]);
                split_tf32(As[r0 + 8][kb + 4], ah[mt][3], al[mt][3]);
            }
            #pragma unroll
            for (int nt = 0; nt < 4; nt++) {
                int nn = warpN + nt * 8 + qr;
                split_tf32(Bs[kb][nn],     bh[nt][0], bl[nt][0]);
                split_tf32(Bs[kb + 4][nn], bh[nt][1], bl[nt][1]);
            }
            #pragma unroll
            for (int mt = 0; mt < 2; mt++)
                #pragma unroll
                for (int nt = 0; nt < 4; nt++) {
                    mma8(acc[mt][nt], ah[mt], bl[nt]);
                    mma8(acc[mt][nt], al[mt], bh[nt]);
                    mma8(acc[mt][nt], ah[mt], bh[nt]);
                }
        }
        __syncthreads();
    }

    // ---- epilogue 1: fp16 output ----
    #pragma unroll
    for (int mt = 0; mt < 2; mt++) {
        int r0 = rowBase + warpM + mt * 16 + qr;
        #pragma unroll
        for (int nt = 0; nt < 4; nt++) {
            int cc = colBase + warpN + nt * 8 + qc * 2;
            if (r0 < n)
                Ch[(size_t)r0 * Mh + (cc >> 1)] = __floats2half2_rn(acc[mt][nt][0], acc[mt][nt][1]);
            if (r0 + 8 < n)
                Ch[(size_t)(r0 + 8) * Mh + (cc >> 1)] = __floats2half2_rn(acc[mt][nt][2], acc[mt][nt][3]);
        }
    }

    // ---- epilogue 2: fused attention logits ----
    float psum[4] = {0.f, 0.f, 0.f, 0.f};
    float pdsum[4] = {0.f, 0.f, 0.f, 0.f};
    #pragma unroll
    for (int mt = 0; mt < 2; mt++)
        #pragma unroll
        for (int nt = 0; nt < 4; nt++) {
            int cl = warpN + nt * 8 + qc * 2;
            float as0 = s_as[cl], as1 = s_as[cl + 1];
            float ad0 = s_ad[cl], ad1 = s_ad[cl + 1];
            psum [mt * 2 + 0] += acc[mt][nt][0] * as0 + acc[mt][nt][1] * as1;
            pdsum[mt * 2 + 0] += acc[mt][nt][0] * ad0 + acc[mt][nt][1] * ad1;
            psum [mt * 2 + 1] += acc[mt][nt][2] * as0 + acc[mt][nt][3] * as1;
            pdsum[mt * 2 + 1] += acc[mt][nt][2] * ad0 + acc[mt][nt][3] * ad1;
        }
    #pragma unroll
    for (int off = 1; off <= 2; off <<= 1)
        #pragma unroll
        for (int j = 0; j < 4; j++) {
            psum[j]  += __shfl_xor_sync(0xffffffffu, psum[j],  off);
            pdsum[j] += __shfl_xor_sync(0xffffffffu, pdsum[j], off);
        }
    float* red_s = &As[0][0];
    float* red_d = &As[0][0] + 128;
    __syncthreads();
    if ((warp & 1) == 0 && qc == 0) {
        #pragma unroll
        for (int j = 0; j < 4; j++) {
            int row = warpM + (j >> 1) * 16 + (j & 1) * 8 + qr;
            red_s[row] = psum[j];
            red_d[row] = pdsum[j];
        }
    }
    __syncthreads();
    if ((warp & 1) == 1 && qc == 0) {
        #pragma unroll
        for (int j = 0; j < 4; j++) {
            int row = warpM + (j >> 1) * 16 + (j & 1) * 8 + qr;
            int grow = rowBase + row;
            if (grow < n) {
                out_s[(size_t)grow * lstride + head] = red_s[row] + psum[j];
                out_d[(size_t)grow * lstride + head] = red_d[row] + pdsum[j];
            }
        }
    }
}

__global__ void sgemm1_kernel(const float* __restrict__ A, const float* __restrict__ B,
                              const float* __restrict__ att_s, const float* __restrict__ att_d,
                              int n) {
    tf32_gemm_body(A, B, g_h1h, n, 128, 128, att_s, att_d, g_a1s, g_a1d, 2);
}
__global__ void sgemm2_kernel(const float* __restrict__ B,
                              const float* __restrict__ att_s, const float* __restrict__ att_d,
                              int n) {
    tf32_gemm_body(g_hmid, B, g_h2h, n, 128, 64, att_s, att_d, g_a2s, g_a2d, 1);
}

// ---------------- layer1 gather: streaming, no shfl ----------------
__global__ void gather1_kernel(const float* __restrict__ b1, int n) {
    int w = (blockIdx.x * blockDim.x + threadIdx.x) >> 5;
    if (w >= n) return;
    int lane = threadIdx.x & 31;
    int c0 = lane * 4;
    float ws0 = __expf(lrelu(g_a1s[2 * w]     + g_a1d[2 * w]));
    float ws1 = __expf(lrelu(g_a1s[2 * w + 1] + g_a1d[2 * w + 1]));
    uint2 us = *(const uint2*)&g_h1h[(size_t)w * 64 + lane * 2];
    float2 f0 = __half22float2(*reinterpret_cast<__half2*>(&us.x));
    float2 f1 = __half22float2(*reinterpret_cast<__half2*>(&us.y));
    float wws = (c0 < 64) ? ws0 : ws1;
    float4 acc = make_float4(f0.x * wws, f0.y * wws, f1.x * wws, f1.y * wws);
    float den0 = ws0, den1 = ws1;
    int start = g_ptr[w], end = g_ptr[w + 1];
    #pragma unroll 4
    for (int j = start; j < end; j++) {
        int s = g_sedge[j].x;
        float2 wv = g_ew1[j];
        uint2 u = *(const uint2*)&g_h1h[(size_t)s * 64 + lane * 2];
        float2 h0 = __half22float2(*reinterpret_cast<__half2*>(&u.x));
        float2 h1 = __half22float2(*reinterpret_cast<__half2*>(&u.y));
        float ww = (c0 < 64) ? wv.x : wv.y;
        acc.x += h0.x * ww; acc.y += h0.y * ww; acc.z += h1.x * ww; acc.w += h1.y * ww;
        den0 += wv.x; den1 += wv.y;
    }
    float r = 1.0f / (((c0 < 64) ? den0 : den1) + EPSQ);
    float4 o;
    o.x = elu1(acc.x * r + b1[c0]);
    o.y = elu1(acc.y * r + b1[c0 + 1]);
    o.z = elu1(acc.z * r + b1[c0 + 2]);
    o.w = elu1(acc.w * r + b1[c0 + 3]);
    *(float4*)&g_hmid[(size_t)w * 128 + c0] = o;
}

// ---------------- fused layer2 gather + final head: 16 nodes / 512-thread block --
__global__ void gather2final_kernel(const float* __restrict__ b2,
                                    const float* __restrict__ lin_w,
                                    const float* __restrict__ lin_b,
                                    float* __restrict__ out, int n) {
    __shared__ float sw[1024];
    __shared__ float st[16][66];
    int tid = threadIdx.x;
    int wid = tid >> 5, lane = tid & 31;
    int nb = blockIdx.x * 16;
    int node = nb + wid;
    sw[tid] = lin_w[tid];
    sw[tid + 512] = lin_w[tid + 512];
    int c0 = lane * 2;
    float2 o = make_float2(0.f, 0.f);
    if (node < n) {
        float ws0 = __expf(lrelu(g_a2s[node] + g_a2d[node]));
        float2 hs = __half22float2(g_h2h[(size_t)node * 32 + lane]);
        float2 acc = make_float2(hs.x * ws0, hs.y * ws0);
        float den = ws0;
        int start = g_ptr[node], end = g_ptr[node + 1];
        #pragma unroll 4
        for (int j = start; j < end; j++) {
            int s = g_sedge[j].x;
            float wv = g_ew2[j];
            float2 h = __half22float2(g_h2h[(size_t)s * 32 + lane]);
            acc.x += h.x * wv; acc.y += h.y * wv;
            den += wv;
        }
        float r = 1.0f / (den + EPSQ);
        o.x = elu1(acc.x * r + b2[c0]);
        o.y = elu1(acc.y * r + b2[c0 + 1]);
    }
    st[wid][c0] = o.x;
    st[wid][c0 + 1] = o.y;
    __syncthreads();
    if (tid < 256) {
        int g = tid >> 4, o16 = tid & 15;
        int nd = nb + g;
        if (nd < n) {
            float acc = lin_b[o16];
            #pragma unroll
            for (int c = 0; c < 64; c++)
                acc += st[g][c] * sw[c * 16 + o16];
            out[(size_t)nd * 16 + o16] = 1.0f / (1.0f + __expf(-acc));
        }
    }
}

// ---------------- launcher ----------------
extern "C" void kernel_launch(void* const* d_in, const int* in_sizes, int n_in,
                              void* d_out, int out_size) {
    const float* x        = (const float*)d_in[0];
    const void*  ei       = d_in[1];
    const float* W1       = (const float*)d_in[2];
    const float* att_src1 = (const float*)d_in[3];
    const float* att_dst1 = (const float*)d_in[4];
    const float* b1       = (const float*)d_in[5];
    const float* W2       = (const float*)d_in[6];
    const float* att_src2 = (const float*)d_in[7];
    const float* att_dst2 = (const float*)d_in[8];
    const float* b2       = (const float*)d_in[9];
    const float* lin_w    = (const float*)d_in[10];
    const float* lin_b    = (const float*)d_in[11];
    float*       out      = (float*)d_out;

    int n = in_sizes[0] / 128;        // 50000
    int E = in_sizes[1] / 2;          // 800000
    int nblk = (n + 1023) / 1024;     // 49 scan tiles
    int gy   = (n + 127) / 128;       // 391 gemm row tiles

    // CSR build (R11 structure: full-grid scatter)
    detzero_kernel<<<(n + 4 + 255) / 256, 256>>>(ei, E, n);
    convert_kernel<<<(E + 255) / 256, 256>>>(ei, E);
    scanA_kernel  <<<nblk, 256>>>(n);
    scanB_kernel  <<<1, 64>>>(nblk);
    scanC_kernel  <<<nblk, 256>>>(n);
    scatter_kernel<<<(E + 255) / 256, 256>>>(E);

    // layer 1
    sgemm1_kernel <<<dim3(2, gy), 256>>>(x, W1, att_src1, att_dst1, n);
    edgew1_kernel <<<(E + 255) / 256, 256>>>(E);
    gather1_kernel<<<(n + 7) / 8, 256>>>(b1, n);
    // layer 2
    sgemm2_kernel <<<dim3(1, gy), 256>>>(W2, att_src2, att_dst2, n);
    edgew2_kernel <<<(E + 255) / 256, 256>>>(E);
    gather2final_kernel<<<(n + 15) / 16, 512>>>(b2, lin_w, lin_b, out, n);
}

// round 14
// speedup vs baseline: 1.3033x; 1.0654x over previous
#include <cuda_runtime.h>
#include <cuda_bf16.h>
#include <cuda_fp16.h>
#include <cstdint>

#define NN 50000
#define EE 800000
#define EPSQ 1e-16f

// ---------------- scratch (static device globals; no allocation) ----------------
__device__ __half2 g_h1h [NN * 64];    // layer1 GEMM out, fp16 (256B/row)
__device__ float   g_a1s [NN * 2];
__device__ float   g_a1d [NN * 2];
__device__ float   g_hmid[NN * 128];   // layer1 final -> layer2 GEMM input (fp32)
__device__ __half2 g_h2h [NN * 32];    // layer2 GEMM out, fp16 (128B/row)
__device__ float   g_a2s [NN];
__device__ float   g_a2d [NN];
__device__ int     g_src [EE];
__device__ int     g_dst [EE];
__device__ int     g_deg [NN + 4];
__device__ int     g_ptr [NN + 8];
__device__ int     g_pos [NN + 8];
__device__ int2    g_sedge[EE];        // (src,dst) sorted by dst
__device__ float2  g_ew1 [EE];         // per-edge softmax weights, layer1 (2 heads)
__device__ float   g_ew2 [EE];         // layer2
__device__ int     g_bsum[64];
__device__ int     g_e64;

__device__ __forceinline__ float lrelu(float x) { return x > 0.f ? x : 0.2f * x; }
__device__ __forceinline__ float elu1(float x)  { return x > 0.f ? x : expm1f(x); }

// ---------------- fused: edge dtype detect (block 0) + zero degree ----------------
__global__ void detzero_kernel(const void* ei, int E, int n) {
    int i = blockIdx.x * blockDim.x + threadIdx.x;
    if (i < n + 4) g_deg[i] = 0;
    if (blockIdx.x == 0) {
        __shared__ int ok;
        if (threadIdx.x == 0) ok = 1;
        __syncthreads();
        int stride = E > 256 ? E / 256 : 1;
        long long idx = (long long)threadIdx.x * stride;
        if (idx < E) {
            long long v = ((const long long*)ei)[idx];
            if (v < 0 || v >= n) ok = 0;
        }
        __syncthreads();
        if (threadIdx.x == 0) g_e64 = ok;
    }
}

// ---------------- convert + degree histogram ----------------
__global__ void convert_kernel(const void* ei, int E) {
    int e = blockIdx.x * blockDim.x + threadIdx.x;
    if (e >= E) return;
    int s, d;
    if (g_e64) {
        const long long* p = (const long long*)ei;
        s = (int)p[e];
        d = (int)p[E + e];
    } else {
        const int* p = (const int*)ei;
        s = p[e];
        d = p[E + e];
    }
    g_src[e] = s;
    g_dst[e] = d;
    atomicAdd(&g_deg[d], 1);
}

// ---------------- scanA: per-1024-tile degree sums ----------------
__global__ void scanA_kernel(int n) {
    int b = blockIdx.x;
    int base = b * 1024 + threadIdx.x * 4;
    int s = 0;
    if (base < n) {
        int4 v = *(const int4*)&g_deg[base];
        s = v.x + ((base + 1 < n) ? v.y : 0) + ((base + 2 < n) ? v.z : 0) + ((base + 3 < n) ? v.w : 0);
    }
    int lane = threadIdx.x & 31, wid = threadIdx.x >> 5;
    #pragma unroll
    for (int off = 16; off >= 1; off >>= 1) s += __shfl_xor_sync(0xffffffffu, s, off);
    __shared__ int ws[8];
    if (lane == 0) ws[wid] = s;
    __syncthreads();
    if (threadIdx.x == 0) {
        int t = 0;
        #pragma unroll
        for (int i = 0; i < 8; i++) t += ws[i];
        g_bsum[b] = t;
    }
}

// ---------------- scanC: in-tile scan + inline block-offset (scanB merged) -------
__global__ void scanC_kernel(int n) {
    int b = blockIdx.x, tid = threadIdx.x;
    int idx0 = b * 1024 + tid * 4;
    int d0 = 0, d1 = 0, d2 = 0, d3 = 0;
    if (idx0 < n) {
        int4 v = *(const int4*)&g_deg[idx0];
        d0 = v.x;
        d1 = (idx0 + 1 < n) ? v.y : 0;
        d2 = (idx0 + 2 < n) ? v.z : 0;
        d3 = (idx0 + 3 < n) ? v.w : 0;
    }
    int tsum = d0 + d1 + d2 + d3;
    int lane = tid & 31, wid = tid >> 5;
    int inc = tsum;
    #pragma unroll
    for (int off = 1; off < 32; off <<= 1) {
        int t = __shfl_up_sync(0xffffffffu, inc, off);
        if (lane >= off) inc += t;
    }
    __shared__ int ws[8], wo[8], s_part[2];
    if (lane == 31) ws[wid] = inc;
    // block offset = sum of g_bsum[0..b-1], computed by warps 0-1 (nblk <= 64)
    if (tid < 64) {
        int v = (tid < b) ? g_bsum[tid] : 0;
        #pragma unroll
        for (int off = 16; off >= 1; off >>= 1) v += __shfl_xor_sync(0xffffffffu, v, off);
        if (lane == 0) s_part[tid >> 5] = v;
    }
    __syncthreads();
    if (tid == 0) {
        int run = 0;
        #pragma unroll
        for (int i = 0; i < 8; i++) { wo[i] = run; run += ws[i]; }
    }
    __syncthreads();
    int base = s_part[0] + s_part[1] + wo[wid] + (inc - tsum);
    int p0 = base, p1 = base + d0, p2 = p1 + d1, p3 = p2 + d2;
    if (idx0 < n) {
        if (idx0 + 3 < n) {
            *(int4*)&g_ptr[idx0] = make_int4(p0, p1, p2, p3);
            *(int4*)&g_pos[idx0] = make_int4(p0, p1, p2, p3);
        } else {
            int pv[4] = {p0, p1, p2, p3};
            for (int i = 0; i < 4 && idx0 + i < n; i++) {
                g_ptr[idx0 + i] = pv[i];
                g_pos[idx0 + i] = pv[i];
            }
        }
        if (idx0 <= n - 1 && n - 1 < idx0 + 4) {
            int pv[4] = {p0, p1, p2, p3};
            int dv[4] = {d0, d1, d2, d3};
            int k = (n - 1) - idx0;
            g_ptr[n] = pv[k] + dv[k];
        }
    }
}

// ---------------- scatter (src,dst) into dst-sorted order (full grid) ----------------
__global__ void scatter_kernel(int E) {
    int e = blockIdx.x * blockDim.x + threadIdx.x;
    if (e >= E) return;
    int d = g_dst[e];
    int p = atomicAdd(&g_pos[d], 1);
    g_sedge[p] = make_int2(g_src[e], d);
}

// ---------------- per-edge softmax weights (CSR order, lane per edge) ----------------
__global__ void edgew1_kernel(int E) {
    int j = blockIdx.x * blockDim.x + threadIdx.x;
    if (j >= E) return;
    int2 e = g_sedge[j];
    float2 as = *(const float2*)&g_a1s[2 * e.x];
    float2 ad = *(const float2*)&g_a1d[2 * e.y];
    g_ew1[j] = make_float2(__expf(lrelu(as.x + ad.x)), __expf(lrelu(as.y + ad.y)));
}

__global__ void edgew2_kernel(int E) {
    int j = blockIdx.x * blockDim.x + threadIdx.x;
    if (j >= E) return;
    int2 e = g_sedge[j];
    g_ew2[j] = __expf(lrelu(g_a2s[e.x] + g_a2d[e.y]));
}

// ---------------- 3xTF32 tensor-core GEMM + fused logits + fp16 output ----------------
__device__ __forceinline__ void split_tf32(float x, uint32_t& hi, uint32_t& lo) {
    uint32_t h;
    asm("cvt.rna.tf32.f32 %0, %1;" : "=r"(h) : "f"(x));
    hi = h;
    lo = __float_as_uint(x - __uint_as_float(h));
}

__device__ __forceinline__ void mma8(float* c, const uint32_t* a, const uint32_t* b) {
    asm volatile(
        "mma.sync.aligned.m16n8k8.row.col.f32.tf32.tf32.f32 "
        "{%0,%1,%2,%3}, {%4,%5,%6,%7}, {%8,%9}, {%0,%1,%2,%3};"
        : "+f"(c[0]), "+f"(c[1]), "+f"(c[2]), "+f"(c[3])
        : "r"(a[0]), "r"(a[1]), "r"(a[2]), "r"(a[3]), "r"(b[0]), "r"(b[1]));
}

__device__ __forceinline__ void tf32_gemm_body(const float* __restrict__ A,
                                               const float* __restrict__ B,
                                               __half2* __restrict__ Ch,
                                               int n, int K, int M,
                                               const float* __restrict__ att_s,
                                               const float* __restrict__ att_d,
                                               float* __restrict__ out_s,
                                               float* __restrict__ out_d,
                                               int lstride) {
    __shared__ float As[128][36];
    __shared__ float Bs[32][68];
    __shared__ float s_as[64], s_ad[64];
    int tid  = threadIdx.x;
    int warp = tid >> 5, lane = tid & 31;
    int qr = lane >> 2, qc = lane & 3;
    int warpM = (warp >> 1) * 32;
    int warpN = (warp & 1) * 32;
    int rowBase = blockIdx.y * 128;
    int colBase = blockIdx.x * 64;
    int head    = blockIdx.x;
    int Mh      = M >> 1;

    if (tid < 64) {
        s_as[tid] = att_s[head * 64 + tid];
        s_ad[tid] = att_d[head * 64 + tid];
    }

    float acc[2][4][4];
    #pragma unroll
    for (int mt = 0; mt < 2; mt++)
        #pragma unroll
        for (int nt = 0; nt < 4; nt++)
            #pragma unroll
            for (int i = 0; i < 4; i++) acc[mt][nt][i] = 0.f;

    float4 pa[4], pb[2];
    #pragma unroll
    for (int i = 0; i < 4; i++) {
        int f = tid + 256 * i;
        int r = f >> 3, c4 = (f & 7) * 4;
        pa[i] = make_float4(0.f, 0.f, 0.f, 0.f);
        if (rowBase + r < n)
            pa[i] = *(const float4*)&A[(size_t)(rowBase + r) * K + c4];
    }
    #pragma unroll
    for (int i = 0; i < 2; i++) {
        int f = tid + 256 * i;
        int r = f >> 4, c4 = (f & 15) * 4;
        pb[i] = *(const float4*)&B[(size_t)r * M + colBase + c4];
    }

    int nsteps = K >> 5;
    for (int t = 0; t < nsteps; t++) {
        #pragma unroll
        for (int i = 0; i < 4; i++) {
            int f = tid + 256 * i;
            *(float4*)&As[f >> 3][(f & 7) * 4] = pa[i];
        }
        #pragma unroll
        for (int i = 0; i < 2; i++) {
            int f = tid + 256 * i;
            *(float4*)&Bs[f >> 4][(f & 15) * 4] = pb[i];
        }
        __syncthreads();
        if (t + 1 < nsteps) {
            int k0 = (t + 1) * 32;
            #pragma unroll
            for (int i = 0; i < 4; i++) {
                int f = tid + 256 * i;
                int r = f >> 3, c4 = (f & 7) * 4;
                pa[i] = make_float4(0.f, 0.f, 0.f, 0.f);
                if (rowBase + r < n)
                    pa[i] = *(const float4*)&A[(size_t)(rowBase + r) * K + k0 + c4];
            }
            #pragma unroll
            for (int i = 0; i < 2; i++) {
                int f = tid + 256 * i;
                int r = f >> 4, c4 = (f & 15) * 4;
                pb[i] = *(const float4*)&B[(size_t)(k0 + r) * M + colBase + c4];
            }
        }
        #pragma unroll
        for (int kk = 0; kk < 4; kk++) {
            int kb = kk * 8 + qc;
            uint32_t ah[2][4], al[2][4], bh[4][2], bl[4][2];
            #pragma unroll
            for (int mt = 0; mt < 2; mt++) {
                int r0 = warpM + mt * 16 + qr;
                split_tf32(As[r0][kb],         ah[mt][0], al[mt][0]);
                split_tf32(As[r0 + 8][kb],     ah[mt][1], al[mt][1]);
                split_tf32(As[r0][kb + 4],     ah[mt][2], al[mt][2]);
                split_tf32(As[r0 + 8][kb + 4], ah[mt][3], al[mt][3]);
            }
            #pragma unroll
            for (int nt = 0; nt < 4; nt++) {
                int nn = warpN + nt * 8 + qr;
                split_tf32(Bs[kb][nn],     bh[nt][0], bl[nt][0]);
                split_tf32(Bs[kb + 4][nn], bh[nt][1], bl[nt][1]);
            }
            #pragma unroll
            for (int mt = 0; mt < 2; mt++)
                #pragma unroll
                for (int nt = 0; nt < 4; nt++) {
                    mma8(acc[mt][nt], ah[mt], bl[nt]);
                    mma8(acc[mt][nt], al[mt], bh[nt]);
                    mma8(acc[mt][nt], ah[mt], bh[nt]);
                }
        }
        __syncthreads();
    }

    // ---- epilogue 1: fp16 output ----
    #pragma unroll
    for (int mt = 0; mt < 2; mt++) {
        int r0 = rowBase + warpM + mt * 16 + qr;
        #pragma unroll
        for (int nt = 0; nt < 4; nt++) {
            int cc = colBase + warpN + nt * 8 + qc * 2;
            if (r0 < n)
                Ch[(size_t)r0 * Mh + (cc >> 1)] = __floats2half2_rn(acc[mt][nt][0], acc[mt][nt][1]);
            if (r0 + 8 < n)
                Ch[(size_t)(r0 + 8) * Mh + (cc >> 1)] = __floats2half2_rn(acc[mt][nt][2], acc[mt][nt][3]);
        }
    }

    // ---- epilogue 2: fused attention logits ----
    float psum[4] = {0.f, 0.f, 0.f, 0.f};
    float pdsum[4] = {0.f, 0.f, 0.f, 0.f};
    #pragma unroll
    for (int mt = 0; mt < 2; mt++)
        #pragma unroll
        for (int nt = 0; nt < 4; nt++) {
            int cl = warpN + nt * 8 + qc * 2;
            float as0 = s_as[cl], as1 = s_as[cl + 1];
            float ad0 = s_ad[cl], ad1 = s_ad[cl + 1];
            psum [mt * 2 + 0] += acc[mt][nt][0] * as0 + acc[mt][nt][1] * as1;
            pdsum[mt * 2 + 0] += acc[mt][nt][0] * ad0 + acc[mt][nt][1] * ad1;
            psum [mt * 2 + 1] += acc[mt][nt][2] * as0 + acc[mt][nt][3] * as1;
            pdsum[mt * 2 + 1] += acc[mt][nt][2] * ad0 + acc[mt][nt][3] * ad1;
        }
    #pragma unroll
    for (int off = 1; off <= 2; off <<= 1)
        #pragma unroll
        for (int j = 0; j < 4; j++) {
            psum[j]  += __shfl_xor_sync(0xffffffffu, psum[j],  off);
            pdsum[j] += __shfl_xor_sync(0xffffffffu, pdsum[j], off);
        }
    float* red_s = &As[0][0];
    float* red_d = &As[0][0] + 128;
    __syncthreads();
    if ((warp & 1) == 0 && qc == 0) {
        #pragma unroll
        for (int j = 0; j < 4; j++) {
            int row = warpM + (j >> 1) * 16 + (j & 1) * 8 + qr;
            red_s[row] = psum[j];
            red_d[row] = pdsum[j];
        }
    }
    __syncthreads();
    if ((warp & 1) == 1 && qc == 0) {
        #pragma unroll
        for (int j = 0; j < 4; j++) {
            int row = warpM + (j >> 1) * 16 + (j & 1) * 8 + qr;
            int grow = rowBase + row;
            if (grow < n) {
                out_s[(size_t)grow * lstride + head] = red_s[row] + psum[j];
                out_d[(size_t)grow * lstride + head] = red_d[row] + pdsum[j];
            }
        }
    }
}

__global__ void sgemm1_kernel(const float* __restrict__ A, const float* __restrict__ B,
                              const float* __restrict__ att_s, const float* __restrict__ att_d,
                              int n) {
    tf32_gemm_body(A, B, g_h1h, n, 128, 128, att_s, att_d, g_a1s, g_a1d, 2);
}
__global__ void sgemm2_kernel(const float* __restrict__ B,
                              const float* __restrict__ att_s, const float* __restrict__ att_d,
                              int n) {
    tf32_gemm_body(g_hmid, B, g_h2h, n, 128, 64, att_s, att_d, g_a2s, g_a2d, 1);
}

// ---------------- layer1 gather: streaming, no shfl ----------------
__global__ void gather1_kernel(const float* __restrict__ b1, int n) {
    int w = (blockIdx.x * blockDim.x + threadIdx.x) >> 5;
    if (w >= n) return;
    int lane = threadIdx.x & 31;
    int c0 = lane * 4;
    float ws0 = __expf(lrelu(g_a1s[2 * w]     + g_a1d[2 * w]));
    float ws1 = __expf(lrelu(g_a1s[2 * w + 1] + g_a1d[2 * w + 1]));
    uint2 us = *(const uint2*)&g_h1h[(size_t)w * 64 + lane * 2];
    float2 f0 = __half22float2(*reinterpret_cast<__half2*>(&us.x));
    float2 f1 = __half22float2(*reinterpret_cast<__half2*>(&us.y));
    float wws = (c0 < 64) ? ws0 : ws1;
    float4 acc = make_float4(f0.x * wws, f0.y * wws, f1.x * wws, f1.y * wws);
    float den0 = ws0, den1 = ws1;
    int start = g_ptr[w], end = g_ptr[w + 1];
    #pragma unroll 4
    for (int j = start; j < end; j++) {
        int s = g_sedge[j].x;
        float2 wv = g_ew1[j];
        uint2 u = *(const uint2*)&g_h1h[(size_t)s * 64 + lane * 2];
        float2 h0 = __half22float2(*reinterpret_cast<__half2*>(&u.x));
        float2 h1 = __half22float2(*reinterpret_cast<__half2*>(&u.y));
        float ww = (c0 < 64) ? wv.x : wv.y;
        acc.x += h0.x * ww; acc.y += h0.y * ww; acc.z += h1.x * ww; acc.w += h1.y * ww;
        den0 += wv.x; den1 += wv.y;
    }
    float r = 1.0f / (((c0 < 64) ? den0 : den1) + EPSQ);
    float4 o;
    o.x = elu1(acc.x * r + b1[c0]);
    o.y = elu1(acc.y * r + b1[c0 + 1]);
    o.z = elu1(acc.z * r + b1[c0 + 2]);
    o.w = elu1(acc.w * r + b1[c0 + 3]);
    *(float4*)&g_hmid[(size_t)w * 128 + c0] = o;
}

// ---------------- fused layer2 gather + final head: 16 nodes / 512-thread block --
__global__ void gather2final_kernel(const float* __restrict__ b2,
                                    const float* __restrict__ lin_w,
                                    const float* __restrict__ lin_b,
                                    float* __restrict__ out, int n) {
    __shared__ float sw[1024];
    __shared__ float st[16][66];
    int tid = threadIdx.x;
    int wid = tid >> 5, lane = tid & 31;
    int nb = blockIdx.x * 16;
    int node = nb + wid;
    sw[tid] = lin_w[tid];
    sw[tid + 512] = lin_w[tid + 512];
    int c0 = lane * 2;
    float2 o = make_float2(0.f, 0.f);
    if (node < n) {
        float ws0 = __expf(lrelu(g_a2s[node] + g_a2d[node]));
        float2 hs = __half22float2(g_h2h[(size_t)node * 32 + lane]);
        float2 acc = make_float2(hs.x * ws0, hs.y * ws0);
        float den = ws0;
        int start = g_ptr[node], end = g_ptr[node + 1];
        #pragma unroll 4
        for (int j = start; j < end; j++) {
            int s = g_sedge[j].x;
            float wv = g_ew2[j];
            float2 h = __half22float2(g_h2h[(size_t)s * 32 + lane]);
            acc.x += h.x * wv; acc.y += h.y * wv;
            den += wv;
        }
        float r = 1.0f / (den + EPSQ);
        o.x = elu1(acc.x * r + b2[c0]);
        o.y = elu1(acc.y * r + b2[c0 + 1]);
    }
    st[wid][c0] = o.x;
    st[wid][c0 + 1] = o.y;
    __syncthreads();
    if (tid < 256) {
        int g = tid >> 4, o16 = tid & 15;
        int nd = nb + g;
        if (nd < n) {
            float acc = lin_b[o16];
            #pragma unroll
            for (int c = 0; c < 64; c++)
                acc += st[g][c] * sw[c * 16 + o16];
            out[(size_t)nd * 16 + o16] = 1.0f / (1.0f + __expf(-acc));
        }
    }
}

// ---------------- launcher ----------------
extern "C" void kernel_launch(void* const* d_in, const int* in_sizes, int n_in,
                              void* d_out, int out_size) {
    const float* x        = (const float*)d_in[0];
    const void*  ei       = d_in[1];
    const float* W1       = (const float*)d_in[2];
    const float* att_src1 = (const float*)d_in[3];
    const float* att_dst1 = (const float*)d_in[4];
    const float* b1       = (const float*)d_in[5];
    const float* W2       = (const float*)d_in[6];
    const float* att_src2 = (const float*)d_in[7];
    const float* att_dst2 = (const float*)d_in[8];
    const float* b2       = (const float*)d_in[9];
    const float* lin_w    = (const float*)d_in[10];
    const float* lin_b    = (const float*)d_in[11];
    float*       out      = (float*)d_out;

    int n = in_sizes[0] / 128;        // 50000
    int E = in_sizes[1] / 2;          // 800000
    int nblk = (n + 1023) / 1024;     // 49 scan tiles
    int gy   = (n + 127) / 128;       // 391 gemm row tiles

    // lazy one-time host resources (no device memory; work per call unchanged)
    static cudaStream_t s_side = nullptr;
    static cudaEvent_t  ev_fork = nullptr, ev_join = nullptr;
    if (s_side == nullptr) {
        cudaStreamCreateWithFlags(&s_side, cudaStreamNonBlocking);
        cudaEventCreateWithFlags(&ev_fork, cudaEventDisableTiming);
        cudaEventCreateWithFlags(&ev_join, cudaEventDisableTiming);
    }

    // fork: CSR build on side stream, sgemm1 on main stream (independent work)
    cudaEventRecord(ev_fork, 0);
    cudaStreamWaitEvent(s_side, ev_fork, 0);

    detzero_kernel<<<(n + 4 + 255) / 256, 256, 0, s_side>>>(ei, E, n);
    convert_kernel<<<(E + 255) / 256, 256, 0, s_side>>>(ei, E);
    scanA_kernel  <<<nblk, 256, 0, s_side>>>(n);
    scanC_kernel  <<<nblk, 256, 0, s_side>>>(n);
    scatter_kernel<<<(E + 255) / 256, 256, 0, s_side>>>(E);
    cudaEventRecord(ev_join, s_side);

    sgemm1_kernel <<<dim3(2, gy), 256>>>(x, W1, att_src1, att_dst1, n);

    // join: edgew1 needs both sgemm1 (logits) and scatter (sedge)
    cudaStreamWaitEvent(0, ev_join, 0);

    edgew1_kernel <<<(E + 255) / 256, 256>>>(E);
    gather1_kernel<<<(n + 7) / 8, 256>>>(b1, n);
    sgemm2_kernel <<<dim3(1, gy), 256>>>(W2, att_src2, att_dst2, n);
    edgew2_kernel <<<(E + 255) / 256, 256>>>(E);
    gather2final_kernel<<<(n + 15) / 16, 512>>>(b2, lin_w, lin_b, out, n);
}

// round 15
// speedup vs baseline: 1.4416x; 1.1061x over previous
#include <cuda_runtime.h>
#include <cuda_bf16.h>
#include <cuda_fp16.h>
#include <cstdint>

#define NN 50000
#define EE 800000
#define EPSQ 1e-16f

// ---------------- scratch (static device globals; no allocation) ----------------
__device__ __half2 g_h1h [NN * 64];    // layer1 GEMM out, fp16 (256B/row)
__device__ float   g_a1s [NN * 2];
__device__ float   g_a1d [NN * 2];
__device__ float   g_hmid[NN * 128];   // layer1 final -> layer2 GEMM input (fp32)
__device__ __half2 g_h2h [NN * 32];    // layer2 GEMM out, fp16 (128B/row)
__device__ float   g_a2s [NN];
__device__ float   g_a2d [NN];
__device__ int     g_src [EE];
__device__ int     g_dst [EE];
__device__ int     g_deg [NN + 4];
__device__ int     g_ptr [NN + 8];
__device__ int     g_pos [NN + 8];
__device__ int2    g_sedge[EE];        // (src,dst) sorted by dst
__device__ float2  g_ew1 [EE];         // per-edge softmax weights, layer1 (2 heads)
__device__ float   g_ew2 [EE];         // layer2
__device__ int     g_bsum[64];
__device__ int     g_e64;

__device__ __forceinline__ float lrelu(float x) { return x > 0.f ? x : 0.2f * x; }
__device__ __forceinline__ float elu1(float x)  { return x > 0.f ? x : expm1f(x); }

// ---------------- fused: edge dtype detect (block 0) + zero degree ----------------
__global__ void detzero_kernel(const void* ei, int E, int n) {
    int i = blockIdx.x * blockDim.x + threadIdx.x;
    if (i < n + 4) g_deg[i] = 0;
    if (blockIdx.x == 0) {
        __shared__ int ok;
        if (threadIdx.x == 0) ok = 1;
        __syncthreads();
        int stride = E > 256 ? E / 256 : 1;
        long long idx = (long long)threadIdx.x * stride;
        if (idx < E) {
            long long v = ((const long long*)ei)[idx];
            if (v < 0 || v >= n) ok = 0;
        }
        __syncthreads();
        if (threadIdx.x == 0) g_e64 = ok;
    }
}

// ---------------- convert + degree histogram ----------------
__global__ void convert_kernel(const void* ei, int E) {
    int e = blockIdx.x * blockDim.x + threadIdx.x;
    if (e >= E) return;
    int s, d;
    if (g_e64) {
        const long long* p = (const long long*)ei;
        s = (int)p[e];
        d = (int)p[E + e];
    } else {
        const int* p = (const int*)ei;
        s = p[e];
        d = p[E + e];
    }
    g_src[e] = s;
    g_dst[e] = d;
    atomicAdd(&g_deg[d], 1);
}

// ---------------- scanA: per-1024-tile degree sums ----------------
__global__ void scanA_kernel(int n) {
    int b = blockIdx.x;
    int base = b * 1024 + threadIdx.x * 4;
    int s = 0;
    if (base < n) {
        int4 v = *(const int4*)&g_deg[base];
        s = v.x + ((base + 1 < n) ? v.y : 0) + ((base + 2 < n) ? v.z : 0) + ((base + 3 < n) ? v.w : 0);
    }
    int lane = threadIdx.x & 31, wid = threadIdx.x >> 5;
    #pragma unroll
    for (int off = 16; off >= 1; off >>= 1) s += __shfl_xor_sync(0xffffffffu, s, off);
    __shared__ int ws[8];
    if (lane == 0) ws[wid] = s;
    __syncthreads();
    if (threadIdx.x == 0) {
        int t = 0;
        #pragma unroll
        for (int i = 0; i < 8; i++) t += ws[i];
        g_bsum[b] = t;
    }
}

// ---------------- scanC: in-tile scan + inline block-offset ----------------
__global__ void scanC_kernel(int n) {
    int b = blockIdx.x, tid = threadIdx.x;
    int idx0 = b * 1024 + tid * 4;
    int d0 = 0, d1 = 0, d2 = 0, d3 = 0;
    if (idx0 < n) {
        int4 v = *(const int4*)&g_deg[idx0];
        d0 = v.x;
        d1 = (idx0 + 1 < n) ? v.y : 0;
        d2 = (idx0 + 2 < n) ? v.z : 0;
        d3 = (idx0 + 3 < n) ? v.w : 0;
    }
    int tsum = d0 + d1 + d2 + d3;
    int lane = tid & 31, wid = tid >> 5;
    int inc = tsum;
    #pragma unroll
    for (int off = 1; off < 32; off <<= 1) {
        int t = __shfl_up_sync(0xffffffffu, inc, off);
        if (lane >= off) inc += t;
    }
    __shared__ int ws[8], wo[8], s_part[2];
    if (lane == 31) ws[wid] = inc;
    if (tid < 64) {
        int v = (tid < b) ? g_bsum[tid] : 0;
        #pragma unroll
        for (int off = 16; off >= 1; off >>= 1) v += __shfl_xor_sync(0xffffffffu, v, off);
        if (lane == 0) s_part[tid >> 5] = v;
    }
    __syncthreads();
    if (tid == 0) {
        int run = 0;
        #pragma unroll
        for (int i = 0; i < 8; i++) { wo[i] = run; run += ws[i]; }
    }
    __syncthreads();
    int base = s_part[0] + s_part[1] + wo[wid] + (inc - tsum);
    int p0 = base, p1 = base + d0, p2 = p1 + d1, p3 = p2 + d2;
    if (idx0 < n) {
        if (idx0 + 3 < n) {
            *(int4*)&g_ptr[idx0] = make_int4(p0, p1, p2, p3);
            *(int4*)&g_pos[idx0] = make_int4(p0, p1, p2, p3);
        } else {
            int pv[4] = {p0, p1, p2, p3};
            for (int i = 0; i < 4 && idx0 + i < n; i++) {
                g_ptr[idx0 + i] = pv[i];
                g_pos[idx0 + i] = pv[i];
            }
        }
        if (idx0 <= n - 1 && n - 1 < idx0 + 4) {
            int pv[4] = {p0, p1, p2, p3};
            int dv[4] = {d0, d1, d2, d3};
            int k = (n - 1) - idx0;
            g_ptr[n] = pv[k] + dv[k];
        }
    }
}

// ---------------- scatter (src,dst) into dst-sorted order (full grid) ----------------
__global__ void scatter_kernel(int E) {
    int e = blockIdx.x * blockDim.x + threadIdx.x;
    if (e >= E) return;
    int d = g_dst[e];
    int p = atomicAdd(&g_pos[d], 1);
    g_sedge[p] = make_int2(g_src[e], d);
}

// ---------------- per-edge softmax weights (CSR order, lane per edge) ----------------
__global__ void edgew1_kernel(int E) {
    int j = blockIdx.x * blockDim.x + threadIdx.x;
    if (j >= E) return;
    int2 e = g_sedge[j];
    float2 as = *(const float2*)&g_a1s[2 * e.x];
    float2 ad = *(const float2*)&g_a1d[2 * e.y];
    g_ew1[j] = make_float2(__expf(lrelu(as.x + ad.x)), __expf(lrelu(as.y + ad.y)));
}

__global__ void edgew2_kernel(int E) {
    int j = blockIdx.x * blockDim.x + threadIdx.x;
    if (j >= E) return;
    int2 e = g_sedge[j];
    g_ew2[j] = __expf(lrelu(g_a2s[e.x] + g_a2d[e.y]));
}

// ---------------- 1xTF32 tensor-core GEMM + fused logits + fp16 output ----------------
// Plain tf32 (single-pass): per-element rel error ~2-3e-4 at h, attenuated ~27x
// through edge-averaging + head contraction + sigmoid (measured with the fp16
// payload experiment) -> final rel_err ~1e-4, inside the 1e-3 gate with margin.
__device__ __forceinline__ uint32_t to_tf32(float x) {
    uint32_t h;
    asm("cvt.rna.tf32.f32 %0, %1;" : "=r"(h) : "f"(x));
    return h;
}

__device__ __forceinline__ void mma8(float* c, const uint32_t* a, const uint32_t* b) {
    asm volatile(
        "mma.sync.aligned.m16n8k8.row.col.f32.tf32.tf32.f32 "
        "{%0,%1,%2,%3}, {%4,%5,%6,%7}, {%8,%9}, {%0,%1,%2,%3};"
        : "+f"(c[0]), "+f"(c[1]), "+f"(c[2]), "+f"(c[3])
        : "r"(a[0]), "r"(a[1]), "r"(a[2]), "r"(a[3]), "r"(b[0]), "r"(b[1]));
}

__device__ __forceinline__ void tf32_gemm_body(const float* __restrict__ A,
                                               const float* __restrict__ B,
                                               __half2* __restrict__ Ch,
                                               int n, int K, int M,
                                               const float* __restrict__ att_s,
                                               const float* __restrict__ att_d,
                                               float* __restrict__ out_s,
                                               float* __restrict__ out_d,
                                               int lstride) {
    __shared__ float As[128][36];
    __shared__ float Bs[32][68];
    __shared__ float s_as[64], s_ad[64];
    int tid  = threadIdx.x;
    int warp = tid >> 5, lane = tid & 31;
    int qr = lane >> 2, qc = lane & 3;
    int warpM = (warp >> 1) * 32;
    int warpN = (warp & 1) * 32;
    int rowBase = blockIdx.y * 128;
    int colBase = blockIdx.x * 64;
    int head    = blockIdx.x;
    int Mh      = M >> 1;

    if (tid < 64) {
        s_as[tid] = att_s[head * 64 + tid];
        s_ad[tid] = att_d[head * 64 + tid];
    }

    float acc[2][4][4];
    #pragma unroll
    for (int mt = 0; mt < 2; mt++)
        #pragma unroll
        for (int nt = 0; nt < 4; nt++)
            #pragma unroll
            for (int i = 0; i < 4; i++) acc[mt][nt][i] = 0.f;

    float4 pa[4], pb[2];
    #pragma unroll
    for (int i = 0; i < 4; i++) {
        int f = tid + 256 * i;
        int r = f >> 3, c4 = (f & 7) * 4;
        pa[i] = make_float4(0.f, 0.f, 0.f, 0.f);
        if (rowBase + r < n)
            pa[i] = *(const float4*)&A[(size_t)(rowBase + r) * K + c4];
    }
    #pragma unroll
    for (int i = 0; i < 2; i++) {
        int f = tid + 256 * i;
        int r = f >> 4, c4 = (f & 15) * 4;
        pb[i] = *(const float4*)&B[(size_t)r * M + colBase + c4];
    }

    int nsteps = K >> 5;
    for (int t = 0; t < nsteps; t++) {
        #pragma unroll
        for (int i = 0; i < 4; i++) {
            int f = tid + 256 * i;
            *(float4*)&As[f >> 3][(f & 7) * 4] = pa[i];
        }
        #pragma unroll
        for (int i = 0; i < 2; i++) {
            int f = tid + 256 * i;
            *(float4*)&Bs[f >> 4][(f & 15) * 4] = pb[i];
        }
        __syncthreads();
        if (t + 1 < nsteps) {
            int k0 = (t + 1) * 32;
            #pragma unroll
            for (int i = 0; i < 4; i++) {
                int f = tid + 256 * i;
                int r = f >> 3, c4 = (f & 7) * 4;
                pa[i] = make_float4(0.f, 0.f, 0.f, 0.f);
                if (rowBase + r < n)
                    pa[i] = *(const float4*)&A[(size_t)(rowBase + r) * K + k0 + c4];
            }
            #pragma unroll
            for (int i = 0; i < 2; i++) {
                int f = tid + 256 * i;
                int r = f >> 4, c4 = (f & 15) * 4;
                pb[i] = *(const float4*)&B[(size_t)(k0 + r) * M + colBase + c4];
            }
        }
        #pragma unroll
        for (int kk = 0; kk < 4; kk++) {
            int kb = kk * 8 + qc;
            uint32_t ah[2][4], bh[4][2];
            #pragma unroll
            for (int mt = 0; mt < 2; mt++) {
                int r0 = warpM + mt * 16 + qr;
                ah[mt][0] = to_tf32(As[r0][kb]);
                ah[mt][1] = to_tf32(As[r0 + 8][kb]);
                ah[mt][2] = to_tf32(As[r0][kb + 4]);
                ah[mt][3] = to_tf32(As[r0 + 8][kb + 4]);
            }
            #pragma unroll
            for (int nt = 0; nt < 4; nt++) {
                int nn = warpN + nt * 8 + qr;
                bh[nt][0] = to_tf32(Bs[kb][nn]);
                bh[nt][1] = to_tf32(Bs[kb + 4][nn]);
            }
            #pragma unroll
            for (int mt = 0; mt < 2; mt++)
                #pragma unroll
                for (int nt = 0; nt < 4; nt++)
                    mma8(acc[mt][nt], ah[mt], bh[nt]);
        }
        __syncthreads();
    }

    // ---- epilogue 1: fp16 output ----
    #pragma unroll
    for (int mt = 0; mt < 2; mt++) {
        int r0 = rowBase + warpM + mt * 16 + qr;
        #pragma unroll
        for (int nt = 0; nt < 4; nt++) {
            int cc = colBase + warpN + nt * 8 + qc * 2;
            if (r0 < n)
                Ch[(size_t)r0 * Mh + (cc >> 1)] = __floats2half2_rn(acc[mt][nt][0], acc[mt][nt][1]);
            if (r0 + 8 < n)
                Ch[(size_t)(r0 + 8) * Mh + (cc >> 1)] = __floats2half2_rn(acc[mt][nt][2], acc[mt][nt][3]);
        }
    }

    // ---- epilogue 2: fused attention logits ----
    float psum[4] = {0.f, 0.f, 0.f, 0.f};
    float pdsum[4] = {0.f, 0.f, 0.f, 0.f};
    #pragma unroll
    for (int mt = 0; mt < 2; mt++)
        #pragma unroll
        for (int nt = 0; nt < 4; nt++) {
            int cl = warpN + nt * 8 + qc * 2;
            float as0 = s_as[cl], as1 = s_as[cl + 1];
            float ad0 = s_ad[cl], ad1 = s_ad[cl + 1];
            psum [mt * 2 + 0] += acc[mt][nt][0] * as0 + acc[mt][nt][1] * as1;
            pdsum[mt * 2 + 0] += acc[mt][nt][0] * ad0 + acc[mt][nt][1] * ad1;
            psum [mt * 2 + 1] += acc[mt][nt][2] * as0 + acc[mt][nt][3] * as1;
            pdsum[mt * 2 + 1] += acc[mt][nt][2] * ad0 + acc[mt][nt][3] * ad1;
        }
    #pragma unroll
    for (int off = 1; off <= 2; off <<= 1)
        #pragma unroll
        for (int j = 0; j < 4; j++) {
            psum[j]  += __shfl_xor_sync(0xffffffffu, psum[j],  off);
            pdsum[j] += __shfl_xor_sync(0xffffffffu, pdsum[j], off);
        }
    float* red_s = &As[0][0];
    float* red_d = &As[0][0] + 128;
    __syncthreads();
    if ((warp & 1) == 0 && qc == 0) {
        #pragma unroll
        for (int j = 0; j < 4; j++) {
            int row = warpM + (j >> 1) * 16 + (j & 1) * 8 + qr;
            red_s[row] = psum[j];
            red_d[row] = pdsum[j];
        }
    }
    __syncthreads();
    if ((warp & 1) == 1 && qc == 0) {
        #pragma unroll
        for (int j = 0; j < 4; j++) {
            int row = warpM + (j >> 1) * 16 + (j & 1) * 8 + qr;
            int grow = rowBase + row;
            if (grow < n) {
                out_s[(size_t)grow * lstride + head] = red_s[row] + psum[j];
                out_d[(size_t)grow * lstride + head] = red_d[row] + pdsum[j];
            }
        }
    }
}

__global__ void sgemm1_kernel(const float* __restrict__ A, const float* __restrict__ B,
                              const float* __restrict__ att_s, const float* __restrict__ att_d,
                              int n) {
    tf32_gemm_body(A, B, g_h1h, n, 128, 128, att_s, att_d, g_a1s, g_a1d, 2);
}
__global__ void sgemm2_kernel(const float* __restrict__ B,
                              const float* __restrict__ att_s, const float* __restrict__ att_d,
                              int n) {
    tf32_gemm_body(g_hmid, B, g_h2h, n, 128, 64, att_s, att_d, g_a2s, g_a2d, 1);
}

// ---------------- layer1 gather: streaming, no shfl ----------------
__global__ void gather1_kernel(const float* __restrict__ b1, int n) {
    int w = (blockIdx.x * blockDim.x + threadIdx.x) >> 5;
    if (w >= n) return;
    int lane = threadIdx.x & 31;
    int c0 = lane * 4;
    float ws0 = __expf(lrelu(g_a1s[2 * w]     + g_a1d[2 * w]));
    float ws1 = __expf(lrelu(g_a1s[2 * w + 1] + g_a1d[2 * w + 1]));
    uint2 us = *(const uint2*)&g_h1h[(size_t)w * 64 + lane * 2];
    float2 f0 = __half22float2(*reinterpret_cast<__half2*>(&us.x));
    float2 f1 = __half22float2(*reinterpret_cast<__half2*>(&us.y));
    float wws = (c0 < 64) ? ws0 : ws1;
    float4 acc = make_float4(f0.x * wws, f0.y * wws, f1.x * wws, f1.y * wws);
    float den0 = ws0, den1 = ws1;
    int start = g_ptr[w], end = g_ptr[w + 1];
    #pragma unroll 4
    for (int j = start; j < end; j++) {
        int s = g_sedge[j].x;
        float2 wv = g_ew1[j];
        uint2 u = *(const uint2*)&g_h1h[(size_t)s * 64 + lane * 2];
        float2 h0 = __half22float2(*reinterpret_cast<__half2*>(&u.x));
        float2 h1 = __half22float2(*reinterpret_cast<__half2*>(&u.y));
        float ww = (c0 < 64) ? wv.x : wv.y;
        acc.x += h0.x * ww; acc.y += h0.y * ww; acc.z += h1.x * ww; acc.w += h1.y * ww;
        den0 += wv.x; den1 += wv.y;
    }
    float r = 1.0f / (((c0 < 64) ? den0 : den1) + EPSQ);
    float4 o;
    o.x = elu1(acc.x * r + b1[c0]);
    o.y = elu1(acc.y * r + b1[c0 + 1]);
    o.z = elu1(acc.z * r + b1[c0 + 2]);
    o.w = elu1(acc.w * r + b1[c0 + 3]);
    *(float4*)&g_hmid[(size_t)w * 128 + c0] = o;
}

// ---------------- fused layer2 gather + final head: 16 nodes / 512-thread block --
__global__ void gather2final_kernel(const float* __restrict__ b2,
                                    const float* __restrict__ lin_w,
                                    const float* __restrict__ lin_b,
                                    float* __restrict__ out, int n) {
    __shared__ float sw[1024];
    __shared__ float st[16][66];
    int tid = threadIdx.x;
    int wid = tid >> 5, lane = tid & 31;
    int nb = blockIdx.x * 16;
    int node = nb + wid;
    sw[tid] = lin_w[tid];
    sw[tid + 512] = lin_w[tid + 512];
    int c0 = lane * 2;
    float2 o = make_float2(0.f, 0.f);
    if (node < n) {
        float ws0 = __expf(lrelu(g_a2s[node] + g_a2d[node]));
        float2 hs = __half22float2(g_h2h[(size_t)node * 32 + lane]);
        float2 acc = make_float2(hs.x * ws0, hs.y * ws0);
        float den = ws0;
        int start = g_ptr[node], end = g_ptr[node + 1];
        #pragma unroll 4
        for (int j = start; j < end; j++) {
            int s = g_sedge[j].x;
            float wv = g_ew2[j];
            float2 h = __half22float2(g_h2h[(size_t)s * 32 + lane]);
            acc.x += h.x * wv; acc.y += h.y * wv;
            den += wv;
        }
        float r = 1.0f / (den + EPSQ);
        o.x = elu1(acc.x * r + b2[c0]);
        o.y = elu1(acc.y * r + b2[c0 + 1]);
    }
    st[wid][c0] = o.x;
    st[wid][c0 + 1] = o.y;
    __syncthreads();
    if (tid < 256) {
        int g = tid >> 4, o16 = tid & 15;
        int nd = nb + g;
        if (nd < n) {
            float acc = lin_b[o16];
            #pragma unroll
            for (int c = 0; c < 64; c++)
                acc += st[g][c] * sw[c * 16 + o16];
            out[(size_t)nd * 16 + o16] = 1.0f / (1.0f + __expf(-acc));
        }
    }
}

// ---------------- launcher ----------------
extern "C" void kernel_launch(void* const* d_in, const int* in_sizes, int n_in,
                              void* d_out, int out_size) {
    const float* x        = (const float*)d_in[0];
    const void*  ei       = d_in[1];
    const float* W1       = (const float*)d_in[2];
    const float* att_src1 = (const float*)d_in[3];
    const float* att_dst1 = (const float*)d_in[4];
    const float* b1       = (const float*)d_in[5];
    const float* W2       = (const float*)d_in[6];
    const float* att_src2 = (const float*)d_in[7];
    const float* att_dst2 = (const float*)d_in[8];
    const float* b2       = (const float*)d_in[9];
    const float* lin_w    = (const float*)d_in[10];
    const float* lin_b    = (const float*)d_in[11];
    float*       out      = (float*)d_out;

    int n = in_sizes[0] / 128;        // 50000
    int E = in_sizes[1] / 2;          // 800000
    int nblk = (n + 1023) / 1024;     // 49 scan tiles
    int gy   = (n + 127) / 128;       // 391 gemm row tiles

    // lazy one-time host resources (no device memory; work per call unchanged)
    static cudaStream_t s_side = nullptr;
    static cudaEvent_t  ev_fork = nullptr, ev_join = nullptr;
    if (s_side == nullptr) {
        cudaStreamCreateWithFlags(&s_side, cudaStreamNonBlocking);
        cudaEventCreateWithFlags(&ev_fork, cudaEventDisableTiming);
        cudaEventCreateWithFlags(&ev_join, cudaEventDisableTiming);
    }

    // fork: CSR build on side stream, sgemm1 on main stream (independent work)
    cudaEventRecord(ev_fork, 0);
    cudaStreamWaitEvent(s_side, ev_fork, 0);

    detzero_kernel<<<(n + 4 + 255) / 256, 256, 0, s_side>>>(ei, E, n);
    convert_kernel<<<(E + 255) / 256, 256, 0, s_side>>>(ei, E);
    scanA_kernel  <<<nblk, 256, 0, s_side>>>(n);
    scanC_kernel  <<<nblk, 256, 0, s_side>>>(n);
    scatter_kernel<<<(E + 255) / 256, 256, 0, s_side>>>(E);
    cudaEventRecord(ev_join, s_side);

    sgemm1_kernel <<<dim3(2, gy), 256>>>(x, W1, att_src1, att_dst1, n);

    // join: edgew1 needs both sgemm1 (logits) and scatter (sedge)
    cudaStreamWaitEvent(0, ev_join, 0);

    edgew1_kernel <<<(E + 255) / 256, 256>>>(E);
    gather1_kernel<<<(n + 7) / 8, 256>>>(b1, n);
    sgemm2_kernel <<<dim3(1, gy), 256>>>(W2, att_src2, att_dst2, n);
    edgew2_kernel <<<(E + 255) / 256, 256>>>(E);
    gather2final_kernel<<<(n + 15) / 16, 512>>>(b2, lin_w, lin_b, out, n);
}